// round 3
// baseline (speedup 1.0000x reference)
#include <cuda_runtime.h>
#include <math.h>

#define TT   512   // T
#define BBAT 64    // B
#define DD   128   // D
#define UU   256   // U
#define G3   768   // 3U
#define NBLK 128
#define TPB  256
#define KTOT (DD + UU)   // 384
#define NCOLS 24         // 3 gates x 8 u per block
#define AT_STRIDE 18     // padded (float2-aligned, conflict-free)

// ---------------- device state ----------------
// phase-1 partials, double-buffered by step parity: [parity][half][b*U+u]
__device__ float g_part[2][2][BBAT * UU];
__device__ unsigned g_barcnt = 0;
__device__ volatile unsigned g_bargen = 0;

// Software grid barrier; all NBLK blocks resident (128 <= 148 SMs, 1 CTA/SM).
// __threadfence (gpu scope) provides release/acquire and flushes L1D.
__device__ __forceinline__ void grid_sync() {
    __syncthreads();
    if (threadIdx.x == 0) {
        unsigned g = g_bargen;
        __threadfence();
        if (atomicAdd(&g_barcnt, 1u) == NBLK - 1) {
            atomicExch(&g_barcnt, 0u);
            __threadfence();
            g_bargen = g + 1;
        } else {
            while (g_bargen == g) { __nanosleep(64); }
        }
        __threadfence();
    }
    __syncthreads();
}

__global__ void __launch_bounds__(TPB, 1) dag_rnn_kernel(
    const float* __restrict__ x,     // (B,T,D)
    const float* __restrict__ cond,  // (B,T,T)
    const float* __restrict__ Win,   // (D,3U)
    const float* __restrict__ Wrec,  // (U,3U)
    const float* __restrict__ bias,  // (2,3U)
    float* __restrict__ out)         // (B,T,U) == H storage
{
    extern __shared__ float smem[];
    float* At  = smem;                          // KTOT * 18      = 6912 f
    float* Ws  = At + KTOT * AT_STRIDE;         // KTOT * 24      = 9216 f
    float* Gsx = Ws + KTOT * NCOLS;             // 16*24          = 384 f
    float* Gsh = Gsx + 16 * NCOLS;              // 16*24          = 384 f

    const int tid = threadIdx.x;
    const int blk = blockIdx.x;

    // phase-1 identity: (batch, j-half)
    const int p1_b    = blk >> 1;
    const int p1_half = blk & 1;

    // phase-2 identity: 4 b-tiles(16) x 32 u-tiles(8)
    const int b0 = (blk >> 5) * 16;
    const int u0 = (blk & 31) * 8;

    // GEMM thread identity (tid < 192): 8 b-pairs x 24 cols
    const int c    = tid % NCOLS;
    const int bp   = tid / NCOLS;
    const int gate = c >> 3;
    const int up   = c & 7;
    const int col  = gate * UU + u0 + up;

    float bx = 0.f, bh = 0.f;
    if (tid < 192) { bx = bias[col]; bh = bias[G3 + col]; }

    // ---- preload W slice (24 cols x 384 k) into smem, once ----
    for (int idx = tid; idx < KTOT * NCOLS; idx += TPB) {
        int k = idx / NCOLS, cc = idx - k * NCOLS;
        int colc = (cc >> 3) * UU + u0 + (cc & 7);
        Ws[k * NCOLS + cc] = (k < DD) ? Win[(size_t)k * G3 + colc]
                                      : Wrec[(size_t)(k - DD) * G3 + colc];
    }
    // first consumer is after an intra-step __syncthreads (and a grid_sync)

    const float invT = 1.0f / (float)TT;

    for (int i = 0; i < TT; ++i) {
        // ============ phase 1: partial over j in [0, i-1) ============
        {
            const int m   = (i > 0) ? (i - 1) : 0;
            const int jlo = p1_half ? (m >> 1) : 0;
            const int jhi = p1_half ? m : (m >> 1);
            const float* crow = cond + ((size_t)p1_b * TT + i) * TT;
            const float* hb   = out + (size_t)p1_b * TT * UU + tid;
            float a0 = 0.f, a1 = 0.f, a2 = 0.f, a3 = 0.f;
            int j = jlo;
            #pragma unroll 4
            for (; j + 4 <= jhi; j += 4) {
                a0 += __ldg(crow + j)     * __ldcg(hb + (size_t)(j)     * UU);
                a1 += __ldg(crow + j + 1) * __ldcg(hb + (size_t)(j + 1) * UU);
                a2 += __ldg(crow + j + 2) * __ldcg(hb + (size_t)(j + 2) * UU);
                a3 += __ldg(crow + j + 3) * __ldcg(hb + (size_t)(j + 3) * UU);
            }
            for (; j < jhi; ++j)
                a0 += __ldg(crow + j) * __ldcg(hb + (size_t)j * UU);
            g_part[i & 1][p1_half][p1_b * UU + tid] = (a0 + a1) + (a2 + a3);
        }
        grid_sync();   // the ONLY grid barrier per step

        // ============ phase 2: A-tile build ============
        for (int idx = tid; idx < 16 * DD; idx += TPB) {
            int bb = idx >> 7, d = idx & (DD - 1);
            At[d * AT_STRIDE + bb] = __ldg(&x[((size_t)(b0 + bb) * TT + i) * DD + d]);
        }
        for (int idx = tid; idx < 16 * UU; idx += TPB) {
            int bb = idx >> 8, u = idx & (UU - 1);
            int gi = (b0 + bb) * UU + u;
            float pre = __ldcg(&g_part[i & 1][0][gi]) + __ldcg(&g_part[i & 1][1][gi]);
            if (i > 0) {
                // peeled j = i-1 term (out[i-1] visible via this step's grid_sync)
                pre += __ldg(&cond[((size_t)(b0 + bb) * TT + i) * TT + (i - 1)])
                     * __ldcg(&out[((size_t)(b0 + bb) * TT + (i - 1)) * UU + u]);
            }
            At[(DD + u) * AT_STRIDE + bb] = pre * invT;   // next_state
        }
        __syncthreads();

        // ============ fused GEMM: [x | h] @ [Win ; Wrec] ============
        if (tid < 192) {
            const float* wsa = Ws + c;
            float aA0 = 0.f, aA1 = 0.f, aB0 = 0.f, aB1 = 0.f;
            #pragma unroll 8
            for (int k = 0; k < DD; ++k) {
                float w  = wsa[k * NCOLS];
                float2 a = *(const float2*)&At[k * AT_STRIDE + 2 * bp];
                aA0 += a.x * w; aA1 += a.y * w;
            }
            #pragma unroll 8
            for (int k = 0; k < UU; ++k) {
                float w  = wsa[(DD + k) * NCOLS];
                float2 a = *(const float2*)&At[(DD + k) * AT_STRIDE + 2 * bp];
                aB0 += a.x * w; aB1 += a.y * w;
            }
            Gsx[(2 * bp)     * NCOLS + c] = aA0 + bx;
            Gsx[(2 * bp + 1) * NCOLS + c] = aA1 + bx;
            Gsh[(2 * bp)     * NCOLS + c] = aB0 + bh;
            Gsh[(2 * bp + 1) * NCOLS + c] = aB1 + bh;
        }
        __syncthreads();

        // ============ gates + output (16b x 8u = 128 threads) ============
        if (tid < 128) {
            int uq = tid & 7, bb = tid >> 3;
            float xz = Gsx[bb * NCOLS + uq],      hz = Gsh[bb * NCOLS + uq];
            float xr = Gsx[bb * NCOLS + 8 + uq],  hr = Gsh[bb * NCOLS + 8 + uq];
            float xh = Gsx[bb * NCOLS + 16 + uq], hh = Gsh[bb * NCOLS + 16 + uq];
            float z  = 1.0f / (1.0f + expf(-(xz + hz)));
            float r  = 1.0f / (1.0f + expf(-(xr + hr)));
            float hc = tanhf(xh + r * hh);
            float h  = At[(DD + u0 + uq) * AT_STRIDE + bb];   // next_state
            float o  = z * h + (1.0f - z) * hc;
            out[((size_t)(b0 + bb) * TT + i) * UU + u0 + uq] = o;
        }
        // no trailing grid_sync: next phase1 touches only out[j<=i-1] and the
        // opposite g_part parity; smem reuse is fenced by next grid_sync's
        // leading __syncthreads.
    }
}

extern "C" void kernel_launch(void* const* d_in, const int* in_sizes, int n_in,
                              void* d_out, int out_size) {
    const float* x    = (const float*)d_in[0];
    const float* cond = (const float*)d_in[1];
    const float* Win  = (const float*)d_in[2];
    const float* Wrec = (const float*)d_in[3];
    const float* bias = (const float*)d_in[4];
    float* out = (float*)d_out;

    const int smem_bytes = (KTOT * AT_STRIDE + KTOT * NCOLS + 2 * 16 * NCOLS) * sizeof(float);
    static bool attr_set = false;
    if (!attr_set) {
        cudaFuncSetAttribute(dag_rnn_kernel,
                             cudaFuncAttributeMaxDynamicSharedMemorySize, smem_bytes);
        attr_set = true;
    }
    dag_rnn_kernel<<<NBLK, TPB, smem_bytes>>>(x, cond, Win, Wrec, bias, out);
}

// round 4
// speedup vs baseline: 1.2987x; 1.2987x over previous
#include <cuda_runtime.h>
#include <math.h>

#define TT   512
#define BBAT 64
#define DD   128
#define UU   256
#define G3   768
#define NBLK 128
#define TPB  256
#define CH   8            // chunk length
#define AT_ST 18          // Ah row stride (float2-aligned, low-conflict)

// ---------------- device scratch ----------------
__device__ float g_xg[(size_t)BBAT * TT * G3];   // x @ W_in + bias0 (precomputed)
__device__ float g_basep[2][BBAT][CH][UU];       // chunk-base partials (two j-halves)
__device__ unsigned g_barcnt = 0;
__device__ volatile unsigned g_bargen = 0;

// Grid barrier: all 128 CTAs resident (1/SM). Release: per-thread
// __threadfence BEFORE arrival (orders every thread's STGs at gpu scope,
// not just thread 0's). Acquire: volatile flag read + fence + bar; all
// cross-block data is read via __ldcg (L2 is the coherence point).
__device__ __forceinline__ void grid_sync() {
    __threadfence();
    __syncthreads();
    if (threadIdx.x == 0) {
        unsigned g = g_bargen;
        if (atomicAdd(&g_barcnt, 1u) == NBLK - 1) {
            atomicExch(&g_barcnt, 0u);
            __threadfence();
            g_bargen = g + 1;
        } else {
            while (g_bargen == g) { __nanosleep(64); }
        }
        __threadfence();
    }
    __syncthreads();
}

// smem layout (floats)
#define WS_OFF   0        // 256*24 = 6144   Wrec slice (persistent)
#define BIG_OFF  6144     // 8192            union: stage0 As / chunk Hs / step Ah
#define CS_OFF   14336    // 512             chunk-gemm cond tile
#define GH_OFF   14848    // 384             h-side preactivations
#define CSM_OFF  15232    // 128             per-step cond stage
#define SMEM_F   15360    // 61440 bytes

__global__ void __launch_bounds__(TPB, 1) dag_rnn_kernel(
    const float* __restrict__ x,     // (B,T,D)
    const float* __restrict__ cond,  // (B,T,T)
    const float* __restrict__ Win,   // (D,3U)
    const float* __restrict__ Wrec,  // (U,3U)
    const float* __restrict__ bias,  // (2,3U)
    float* __restrict__ out)         // (B,T,U) == H storage
{
    extern __shared__ float smem[];
    float* Ws  = smem + WS_OFF;
    float* BIG = smem + BIG_OFF;
    float* Cs  = smem + CS_OFF;
    float* Gh  = smem + GH_OFF;
    float* Csm = smem + CSM_OFF;

    const int tid = threadIdx.x;
    const int blk = blockIdx.x;

    // per-step identity: 4 b-tiles(16) x 32 u-tiles(8)
    const int b0 = (blk >> 5) * 16;
    const int u0 = (blk & 31) * 8;

    // hg-GEMM identity (tid<192): 8 b-pairs x 24 cols (3 gates x 8 u)
    const int c    = tid % 24;
    const int bp   = tid / 24;
    const int gcol = (c >> 3) * UU + u0 + (c & 7);
    float bh = 0.f;
    if (tid < 192) bh = bias[G3 + gcol];

    // ---- preload Wrec slice [256][24] ----
    for (int idx = tid; idx < UU * 24; idx += TPB) {
        int k = idx / 24, cc = idx - k * 24;
        int colc = (cc >> 3) * UU + u0 + (cc & 7);
        Ws[idx] = Wrec[(size_t)k * G3 + colc];
    }

    // ================= stage 0: g_xg = x @ Win + bias0 =================
    {
        float* As = BIG;                       // 32 x 128
        const float bz  = bias[tid];
        const float br  = bias[UU + tid];
        const float bhh = bias[2 * UU + tid];
        const int row0 = blk * 256;            // 256 (b,t)-rows per block
        for (int rt = 0; rt < 8; ++rt) {
            const int rbase = row0 + rt * 32;
            __syncthreads();
            for (int idx = tid; idx < 32 * DD; idx += TPB)
                As[idx] = x[(size_t)rbase * DD + idx];
            __syncthreads();
            for (int rs = 0; rs < 4; ++rs) {
                float a0[8], a1[8], a2[8];
                #pragma unroll
                for (int r = 0; r < 8; ++r) { a0[r] = 0.f; a1[r] = 0.f; a2[r] = 0.f; }
                const float* asr = As + (rs * 8) * DD;
                #pragma unroll 4
                for (int k = 0; k < DD; ++k) {
                    float w0 = __ldg(&Win[(size_t)k * G3 + tid]);
                    float w1 = __ldg(&Win[(size_t)k * G3 + UU + tid]);
                    float w2 = __ldg(&Win[(size_t)k * G3 + 2 * UU + tid]);
                    #pragma unroll
                    for (int r = 0; r < 8; ++r) {
                        float a = asr[r * DD + k];          // broadcast LDS
                        a0[r] += a * w0; a1[r] += a * w1; a2[r] += a * w2;
                    }
                }
                #pragma unroll
                for (int r = 0; r < 8; ++r) {
                    size_t ro = (size_t)(rbase + rs * 8 + r) * G3;
                    g_xg[ro + tid]          = a0[r] + bz;
                    g_xg[ro + UU + tid]     = a1[r] + br;
                    g_xg[ro + 2 * UU + tid] = a2[r] + bhh;
                }
            }
        }
    }
    grid_sync();

    const float invT = 1.0f / (float)TT;

    for (int c0 = 0; c0 < TT; c0 += CH) {
        // ---------- chunk-base GEMM: 64 batches x 2 j-halves ----------
        if (c0 > 0) {
            float* Hs = BIG;                   // up to 32 x 256
            const int cb   = blk >> 1;
            const int jh   = blk & 1;
            const int kb   = c0 >> 1;
            const int jbeg = jh * kb;
            const float* hrow = out  + ((size_t)cb * TT + jbeg) * UU;
            const float* crow = cond + ((size_t)cb * TT + c0) * TT + jbeg;

            float acc[2][8];
            #pragma unroll
            for (int a = 0; a < 2; ++a)
                #pragma unroll
                for (int q = 0; q < 8; ++q) acc[a][q] = 0.f;

            const int lg = tid >> 5;           // active threads: lg 0..3
            const int ug = tid & 31;

            for (int jt = 0; jt < kb; jt += 32) {
                const int jn = (kb - jt < 32) ? (kb - jt) : 32;
                __syncthreads();
                for (int idx = tid; idx < jn * UU; idx += TPB)
                    Hs[idx] = __ldcg(&hrow[(size_t)jt * UU + idx]);
                {
                    int l = tid >> 5, jj = tid & 31;      // 256 = 8l x 32jj
                    if (jj < jn)
                        Cs[jj * CH + l] = __ldg(&crow[(size_t)l * TT + jt + jj]);
                }
                __syncthreads();
                if (tid < 128) {
                    for (int jj = 0; jj < jn; ++jj) {
                        float cv0 = Cs[jj * CH + lg];
                        float cv1 = Cs[jj * CH + lg + 4];
                        const float4* h4 = (const float4*)&Hs[jj * UU + ug * 8];
                        float4 ha = h4[0], hb2 = h4[1];
                        acc[0][0] += cv0 * ha.x;  acc[0][1] += cv0 * ha.y;
                        acc[0][2] += cv0 * ha.z;  acc[0][3] += cv0 * ha.w;
                        acc[0][4] += cv0 * hb2.x; acc[0][5] += cv0 * hb2.y;
                        acc[0][6] += cv0 * hb2.z; acc[0][7] += cv0 * hb2.w;
                        acc[1][0] += cv1 * ha.x;  acc[1][1] += cv1 * ha.y;
                        acc[1][2] += cv1 * ha.z;  acc[1][3] += cv1 * ha.w;
                        acc[1][4] += cv1 * hb2.x; acc[1][5] += cv1 * hb2.y;
                        acc[1][6] += cv1 * hb2.z; acc[1][7] += cv1 * hb2.w;
                    }
                }
            }
            if (tid < 128) {
                #pragma unroll
                for (int li = 0; li < 2; ++li) {
                    const int l = lg + li * 4;
                    float* dst = &g_basep[jh][cb][l][ug * 8];
                    ((float4*)dst)[0] = make_float4(acc[li][0], acc[li][1],
                                                    acc[li][2], acc[li][3]);
                    ((float4*)dst)[1] = make_float4(acc[li][4], acc[li][5],
                                                    acc[li][6], acc[li][7]);
                }
            }
            grid_sync();
        }

        // ---------------- sequential steps within chunk ----------------
        for (int l = 0; l < CH; ++l) {
            const int i = c0 + l;
            float* Ah = BIG;                   // next_state, [u][bb], stride 18

            // stage correction conds: Csm[jj*16+bb], jj<l
            {
                const int jj = tid >> 4, bb = tid & 15;
                if (jj < l)
                    Csm[tid] = __ldg(&cond[((size_t)(b0 + bb) * TT + i) * TT + c0 + jj]);
            }
            __syncthreads();

            // correction + base: thread = u (tid), loop bb
            {
                float acc[16];
                if (c0 > 0) {
                    #pragma unroll
                    for (int bb = 0; bb < 16; ++bb)
                        acc[bb] = __ldcg(&g_basep[0][b0 + bb][l][tid])
                                + __ldcg(&g_basep[1][b0 + bb][l][tid]);
                } else {
                    #pragma unroll
                    for (int bb = 0; bb < 16; ++bb) acc[bb] = 0.f;
                }
                const float* ob = out + (size_t)b0 * TT * UU + (size_t)c0 * UU + tid;
                for (int jj = 0; jj < l; ++jj) {
                    #pragma unroll
                    for (int bb = 0; bb < 16; ++bb)
                        acc[bb] += Csm[jj * 16 + bb]
                                 * __ldcg(&ob[(size_t)bb * (TT * UU) + (size_t)jj * UU]);
                }
                #pragma unroll
                for (int bb = 0; bb < 16; ++bb)
                    Ah[tid * AT_ST + bb] = acc[bb] * invT;
            }
            __syncthreads();

            // hg = next @ Wrec  (K=256), tid<192, 2 outputs each
            if (tid < 192) {
                const float* wsa = Ws + c;
                float g0 = 0.f, g1 = 0.f;
                #pragma unroll 8
                for (int k = 0; k < UU; ++k) {
                    float w  = wsa[k * 24];
                    float2 a = *(const float2*)&Ah[k * AT_ST + 2 * bp];
                    g0 += a.x * w; g1 += a.y * w;
                }
                Gh[(2 * bp) * 24 + c]     = g0 + bh;
                Gh[(2 * bp + 1) * 24 + c] = g1 + bh;
            }
            __syncthreads();

            // gates + output: 16b x 8u
            if (tid < 128) {
                const int uq = tid & 7, bb = tid >> 3;
                const size_t xo = ((size_t)(b0 + bb) * TT + i) * G3 + u0 + uq;
                float xz = __ldg(&g_xg[xo]);
                float xr = __ldg(&g_xg[xo + UU]);
                float xh = __ldg(&g_xg[xo + 2 * UU]);
                float hz = Gh[bb * 24 + uq];
                float hr = Gh[bb * 24 + 8 + uq];
                float hh = Gh[bb * 24 + 16 + uq];
                float z  = 1.0f / (1.0f + __expf(-(xz + hz)));
                float r  = 1.0f / (1.0f + __expf(-(xr + hr)));
                float hc = tanhf(xh + r * hh);
                float h  = Ah[(u0 + uq) * AT_ST + bb];   // next_state
                out[((size_t)(b0 + bb) * TT + i) * UU + u0 + uq]
                    = z * h + (1.0f - z) * hc;
            }
            grid_sync();
        }
    }
}

extern "C" void kernel_launch(void* const* d_in, const int* in_sizes, int n_in,
                              void* d_out, int out_size) {
    const float* x    = (const float*)d_in[0];
    const float* cond = (const float*)d_in[1];
    const float* Win  = (const float*)d_in[2];
    const float* Wrec = (const float*)d_in[3];
    const float* bias = (const float*)d_in[4];
    float* out = (float*)d_out;

    const int smem_bytes = SMEM_F * sizeof(float);
    static bool attr_set = false;
    if (!attr_set) {
        cudaFuncSetAttribute(dag_rnn_kernel,
                             cudaFuncAttributeMaxDynamicSharedMemorySize, smem_bytes);
        attr_set = true;
    }
    dag_rnn_kernel<<<NBLK, TPB, smem_bytes>>>(x, cond, Win, Wrec, bias, out);
}